// round 1
// baseline (speedup 1.0000x reference)
#include <cuda_runtime.h>
#include <math.h>

#define BPB 288            // blocks per batch (reduction kernel)
#define THREADS 256
#define NBATCH 4
#define NELEM (192*192*192)        // 7,077,888 per batch
#define NVEC  (NELEM/4)            // 1,769,472 float4 per batch

// scratch: per-block partial sums [batch][block][5]
__device__ float g_partials[NBATCH * BPB * 5];

__device__ __forceinline__ float warp_sum(float v) {
    #pragma unroll
    for (int o = 16; o > 0; o >>= 1)
        v += __shfl_xor_sync(0xFFFFFFFFu, v, o);
    return v;
}

__global__ __launch_bounds__(THREADS)
void ncc_reduce1(const float4* __restrict__ J4,   // y_pred
                 const float4* __restrict__ I4)   // y_true
{
    const int b = blockIdx.y;
    const float4* __restrict__ Ib = I4 + (size_t)b * NVEC;
    const float4* __restrict__ Jb = J4 + (size_t)b * NVEC;

    float sI = 0.f, sJ = 0.f, sII = 0.f, sJJ = 0.f, sIJ = 0.f;

    for (int i = blockIdx.x * THREADS + threadIdx.x; i < NVEC;
         i += BPB * THREADS) {
        float4 a = Ib[i];
        float4 c = Jb[i];
        sI  += a.x + a.y + a.z + a.w;
        sJ  += c.x + c.y + c.z + c.w;
        sII += a.x*a.x + a.y*a.y + a.z*a.z + a.w*a.w;
        sJJ += c.x*c.x + c.y*c.y + c.z*c.z + c.w*c.w;
        sIJ += a.x*c.x + a.y*c.y + a.z*c.z + a.w*c.w;
    }

    // intra-warp reduce
    sI  = warp_sum(sI);
    sJ  = warp_sum(sJ);
    sII = warp_sum(sII);
    sJJ = warp_sum(sJJ);
    sIJ = warp_sum(sIJ);

    __shared__ float sm[5][THREADS / 32];
    const int lane = threadIdx.x & 31;
    const int wid  = threadIdx.x >> 5;
    if (lane == 0) {
        sm[0][wid] = sI;  sm[1][wid] = sJ;  sm[2][wid] = sII;
        sm[3][wid] = sJJ; sm[4][wid] = sIJ;
    }
    __syncthreads();

    if (wid == 0) {
        const int nw = THREADS / 32;
        float v0 = (lane < nw) ? sm[0][lane] : 0.f;
        float v1 = (lane < nw) ? sm[1][lane] : 0.f;
        float v2 = (lane < nw) ? sm[2][lane] : 0.f;
        float v3 = (lane < nw) ? sm[3][lane] : 0.f;
        float v4 = (lane < nw) ? sm[4][lane] : 0.f;
        v0 = warp_sum(v0); v1 = warp_sum(v1); v2 = warp_sum(v2);
        v3 = warp_sum(v3); v4 = warp_sum(v4);
        if (lane == 0) {
            float* p = &g_partials[(b * BPB + blockIdx.x) * 5];
            p[0] = v0; p[1] = v1; p[2] = v2; p[3] = v3; p[4] = v4;
        }
    }
}

__global__ __launch_bounds__(THREADS)
void ncc_reduce2(float* __restrict__ out)
{
    const int b = blockIdx.x;
    float sI = 0.f, sJ = 0.f, sII = 0.f, sJJ = 0.f, sIJ = 0.f;

    for (int i = threadIdx.x; i < BPB; i += THREADS) {
        const float* p = &g_partials[(b * BPB + i) * 5];
        sI += p[0]; sJ += p[1]; sII += p[2]; sJJ += p[3]; sIJ += p[4];
    }

    sI  = warp_sum(sI);
    sJ  = warp_sum(sJ);
    sII = warp_sum(sII);
    sJJ = warp_sum(sJJ);
    sIJ = warp_sum(sIJ);

    __shared__ float sm[5][THREADS / 32];
    const int lane = threadIdx.x & 31;
    const int wid  = threadIdx.x >> 5;
    if (lane == 0) {
        sm[0][wid] = sI;  sm[1][wid] = sJ;  sm[2][wid] = sII;
        sm[3][wid] = sJJ; sm[4][wid] = sIJ;
    }
    __syncthreads();

    if (threadIdx.x == 0) {
        const int nw = THREADS / 32;
        float tI = 0.f, tJ = 0.f, tII = 0.f, tJJ = 0.f, tIJ = 0.f;
        for (int w = 0; w < nw; w++) {
            tI += sm[0][w]; tJ += sm[1][w]; tII += sm[2][w];
            tJJ += sm[3][w]; tIJ += sm[4][w];
        }
        const float n = (float)NELEM;
        float cross = tIJ - tI * tJ / n;
        float Ivar  = tII - tI * tI / n;
        float Jvar  = tJJ - tJ * tJ / n;
        out[b] = cross / (sqrtf(Ivar) * sqrtf(Jvar) + 1e-5f);
    }
}

extern "C" void kernel_launch(void* const* d_in, const int* in_sizes, int n_in,
                              void* d_out, int out_size)
{
    const float4* y_pred = (const float4*)d_in[0];  // Ji
    const float4* y_true = (const float4*)d_in[1];  // Ii
    float* out = (float*)d_out;

    dim3 grid1(BPB, NBATCH);
    ncc_reduce1<<<grid1, THREADS>>>(y_pred, y_true);
    ncc_reduce2<<<NBATCH, THREADS>>>(out);
}